// round 8
// baseline (speedup 1.0000x reference)
#include <cuda_runtime.h>
#include <math.h>
#include <stdint.h>

#define NNODES 50000
#define NEDGES 500000
#define FDIM   128
#define CLS    40

// ---------------- scratch (static device globals; no allocation) ------------
__device__ float g_A   [NNODES * FDIM];   // A' = x @ W_top + b_pre (fp32)
__device__ float g_B   [NNODES * FDIM];   // B  = x @ W_bot        (fp32)
__device__ float g_S   [NNODES * FDIM];   // SUM aggregator  (fp32)
__device__ float g_M   [NNODES * FDIM];   // MAX aggregator  (fp32)
__device__ float g_H   [NNODES * FDIM];   // hidden after layer 1 (fp32)
__device__ float g_H2  [NNODES * FDIM];   // hidden after layer 2 (fp32)
__device__ float g_IC  [NNODES + 128];    // 1/max(cnt,1) per node (padded)
__device__ float g_Wf1 [513 * FDIM];      // fused W' layer 1 (+bias row, fp32)
__device__ float g_Wf2 [513 * FDIM];      // fused W' layer 2 (+bias row, fp32)
__device__ float g_WpreR[2 * 256 * FDIM]; // tf32-rounded w1_pre, w2_pre
__device__ float g_WoR [FDIM * CLS];      // tf32-rounded w_out
__device__ int   g_hist[NNODES];
__device__ int   g_off [NNODES + 1];
__device__ int   g_cur [NNODES];
__device__ int   g_ssrc[NEDGES];          // src ids grouped (counting-sorted) by dst

// ---------------- helpers ---------------------------------------------------
__device__ __forceinline__ float tf32r(float x) {
    unsigned u;
    asm("cvt.rna.tf32.f32 %0, %1;" : "=r"(u) : "f"(x));
    return __uint_as_float(u);
}

__device__ __forceinline__ unsigned tf32u(float x) {
    unsigned u;
    asm("cvt.rna.tf32.f32 %0, %1;" : "=r"(u) : "f"(x));
    return u;
}

__device__ __forceinline__ void cpasync16(void* dst, const void* src, bool pred) {
    unsigned sa = (unsigned)__cvta_generic_to_shared(dst);
    int sz = pred ? 16 : 0;
    asm volatile("cp.async.cg.shared.global [%0], [%1], 16, %2;\n"
                 :: "r"(sa), "l"(src), "r"(sz));
}

__device__ __forceinline__ void mma_tf32(float* c, const unsigned* a,
                                         unsigned b0, unsigned b1) {
    asm volatile(
        "mma.sync.aligned.m16n8k8.row.col.f32.tf32.tf32.f32 "
        "{%0,%1,%2,%3}, {%4,%5,%6,%7}, {%8,%9}, {%0,%1,%2,%3};"
        : "+f"(c[0]), "+f"(c[1]), "+f"(c[2]), "+f"(c[3])
        : "r"(a[0]), "r"(a[1]), "r"(a[2]), "r"(a[3]), "r"(b0), "r"(b1));
}

// ---------------- graph preprocessing ---------------------------------------
__global__ void hist_kernel(const int* __restrict__ dst) {
    int i = blockIdx.x * blockDim.x + threadIdx.x;
    if (i < NEDGES) atomicAdd(&g_hist[dst[i]], 1);
}

__global__ void scan_kernel() {  // 1 block, 1024 threads
    __shared__ int s[1024];
    const int t = threadIdx.x;
    const int chunk = (NNODES + 1023) / 1024;
    int beg = t * chunk;
    int end = beg + chunk; if (end > NNODES) end = NNODES;
    int sum = 0;
    for (int i = beg; i < end; i++) sum += g_hist[i];
    s[t] = sum;
    __syncthreads();
    for (int d = 1; d < 1024; d <<= 1) {
        int v = (t >= d) ? s[t - d] : 0;
        __syncthreads();
        s[t] += v;
        __syncthreads();
    }
    int run = (t > 0) ? s[t - 1] : 0;
    for (int i = beg; i < end; i++) { g_off[i] = run; run += g_hist[i]; }
    if (t == 0) g_off[NNODES] = NEDGES;
}

__global__ void scatter_kernel(const int* __restrict__ src, const int* __restrict__ dst) {
    int i = blockIdx.x * blockDim.x + threadIdx.x;
    if (i >= NEDGES) return;
    int d = dst[i];
    int p = g_off[d] + atomicAdd(&g_cur[d], 1);
    g_ssrc[p] = src[i];
}

// tf32-round all weight matrices in a single launch
#define CVT_N1 (256 * FDIM)
#define CVT_N2 (256 * FDIM)
#define CVT_N3 (FDIM * CLS)
__global__ void cvt_all_kernel(const float* __restrict__ w1,
                               const float* __restrict__ w2,
                               const float* __restrict__ wo) {
    int i = blockIdx.x * blockDim.x + threadIdx.x;
    if (i < CVT_N1) g_WpreR[i] = tf32r(w1[i]);
    else if (i < CVT_N1 + CVT_N2) g_WpreR[i] = tf32r(w2[i - CVT_N1]);
    else if (i < CVT_N1 + CVT_N2 + CVT_N3) g_WoR[i - CVT_N1 - CVT_N2] =
        tf32r(wo[i - CVT_N1 - CVT_N2]);
}

// ---------------- aggregation (warp/node, float4 lanes, unroll 4) ------------
__global__ void aggregate_kernel() {
    int node = (blockIdx.x * blockDim.x + threadIdx.x) >> 5;
    if (node >= NNODES) return;
    int lane = threadIdx.x & 31;
    int beg = g_off[node], end = g_off[node + 1];
    const float4* Bv = (const float4*)g_B;
    float4 s = make_float4(0.f, 0.f, 0.f, 0.f);
    float4 m = make_float4(-3.4e38f, -3.4e38f, -3.4e38f, -3.4e38f);
    int e = beg;
    for (; e + 3 < end; e += 4) {
        int sv0 = __ldg(&g_ssrc[e]);
        int sv1 = __ldg(&g_ssrc[e + 1]);
        int sv2 = __ldg(&g_ssrc[e + 2]);
        int sv3 = __ldg(&g_ssrc[e + 3]);
        float4 v0 = __ldg(&Bv[(size_t)sv0 * 32 + lane]);
        float4 v1 = __ldg(&Bv[(size_t)sv1 * 32 + lane]);
        float4 v2 = __ldg(&Bv[(size_t)sv2 * 32 + lane]);
        float4 v3 = __ldg(&Bv[(size_t)sv3 * 32 + lane]);
        s.x += (v0.x + v1.x) + (v2.x + v3.x);
        s.y += (v0.y + v1.y) + (v2.y + v3.y);
        s.z += (v0.z + v1.z) + (v2.z + v3.z);
        s.w += (v0.w + v1.w) + (v2.w + v3.w);
        m.x = fmaxf(m.x, fmaxf(fmaxf(v0.x, v1.x), fmaxf(v2.x, v3.x)));
        m.y = fmaxf(m.y, fmaxf(fmaxf(v0.y, v1.y), fmaxf(v2.y, v3.y)));
        m.z = fmaxf(m.z, fmaxf(fmaxf(v0.z, v1.z), fmaxf(v2.z, v3.z)));
        m.w = fmaxf(m.w, fmaxf(fmaxf(v0.w, v1.w), fmaxf(v2.w, v3.w)));
    }
    for (; e < end; e++) {
        int sv = __ldg(&g_ssrc[e]);
        float4 v = __ldg(&Bv[(size_t)sv * 32 + lane]);
        s.x += v.x; s.y += v.y; s.z += v.z; s.w += v.w;
        m.x = fmaxf(m.x, v.x); m.y = fmaxf(m.y, v.y);
        m.z = fmaxf(m.z, v.z); m.w = fmaxf(m.w, v.w);
    }
    size_t o = (size_t)node * 32 + lane;
    float c = (float)(end - beg);
    float ic = 1.f / fmaxf(c, 1.f);
    if (lane == 0) g_IC[node] = ic;
    float4 a = ((const float4*)g_A)[o];
    float4 t;
    t.x = fmaf(c, a.x, s.x); t.y = fmaf(c, a.y, s.y);
    t.z = fmaf(c, a.z, s.z); t.w = fmaf(c, a.w, s.w);
    ((float4*)g_S)[o] = t;
    bool nz = (c > 0.f);
    float4 mx;
    mx.x = nz ? (a.x + m.x) : 0.f; mx.y = nz ? (a.y + m.y) : 0.f;
    mx.z = nz ? (a.z + m.z) : 0.f; mx.w = nz ? (a.w + m.w) : 0.f;
    ((float4*)g_M)[o] = mx;
}

// ---------------- W' = [w_post; b_post] @ w_lin (+ b_lin on bias row) -------
__global__ void fuse_kernel(const float* __restrict__ wpost, const float* __restrict__ bpost,
                            const float* __restrict__ wlin,  const float* __restrict__ blin,
                            float* __restrict__ wf) {
    __shared__ float srow[FDIM];
    int r = blockIdx.x;    // 0..512
    int c = threadIdx.x;   // 0..127
    const float* row = (r < 512) ? (wpost + (size_t)r * FDIM) : bpost;
    srow[c] = row[c];
    __syncthreads();
    float acc = (r == 512) ? blin[c] : 0.f;
    #pragma unroll 8
    for (int k = 0; k < FDIM; k++) acc = fmaf(srow[k], wlin[k * FDIM + c], acc);
    wf[r * FDIM + c] = (r < 512) ? tf32r(acc) : acc;  // bias row stays fp32
}

// ---------------- TF32 tensor-core GEMM (templated M tile) -------------------
// MROWS=128: 8 warps 4(M)x2(N), warp tile 32x64 (NT=8). Used for pre-GEMMs
//   (gridDim.x==2 selects weight half + output; dual-output trick).
// MROWS=64 : 8 warps 2(M)x4(N), warp tile 32x32 (NT=4). Used for cat-GEMMs:
//   halves block M so grid 782 -> ~2.64 rounds of half-cost blocks instead of
//   2 rounds with a 34% idle tail. A traffic unchanged; only tiny W re-read.
// SCALE variant applies per-row ic to the mean segment only (compiled out
// elsewhere). Per-output accumulation order identical for both MROWS.
#define ASTRIDE 36
#define BSTRIDE 136

struct GemmSrcs { const float* s[4]; };

template<int NT, bool SCALE>
__device__ __forceinline__ void mma_block(const float* __restrict__ As,
                                          const float* __restrict__ Bs,
                                          float (*acc)[NT][4],
                                          int wm, int wn, int fr, int fc,
                                          const float* fs) {
    #pragma unroll
    for (int kk = 0; kk < 32; kk += 8) {
        float v0 = As[(wm + fr)      * ASTRIDE + kk + fc];
        float v1 = As[(wm + fr + 8)  * ASTRIDE + kk + fc];
        float v2 = As[(wm + fr)      * ASTRIDE + kk + fc + 4];
        float v3 = As[(wm + fr + 8)  * ASTRIDE + kk + fc + 4];
        float v4 = As[(wm + fr + 16) * ASTRIDE + kk + fc];
        float v5 = As[(wm + fr + 24) * ASTRIDE + kk + fc];
        float v6 = As[(wm + fr + 16) * ASTRIDE + kk + fc + 4];
        float v7 = As[(wm + fr + 24) * ASTRIDE + kk + fc + 4];
        if (SCALE) {
            v0 *= fs[0]; v1 *= fs[1]; v2 *= fs[0]; v3 *= fs[1];
            v4 *= fs[2]; v5 *= fs[3]; v6 *= fs[2]; v7 *= fs[3];
        }
        unsigned af0[4] = {tf32u(v0), tf32u(v1), tf32u(v2), tf32u(v3)};
        unsigned af1[4] = {tf32u(v4), tf32u(v5), tf32u(v6), tf32u(v7)};
        #pragma unroll
        for (int nt = 0; nt < NT; nt++) {
            int n0 = wn + nt * 8;
            unsigned b0 = __float_as_uint(Bs[(kk + fc)     * BSTRIDE + n0 + fr]);
            unsigned b1 = __float_as_uint(Bs[(kk + 4 + fc) * BSTRIDE + n0 + fr]);
            mma_tf32(acc[0][nt], af0, b0, b1);
            mma_tf32(acc[1][nt], af1, b0, b1);
        }
    }
}

template<int MROWS>
__global__ __launch_bounds__(256, 2)
void mma_gemm(GemmSrcs srcs, const float* __restrict__ W,
              const float* __restrict__ bias0,
              float* outA, float* outB,
              const float* __restrict__ icvec, int meanSeg,
              int M, int nIter, int relu) {
    constexpr int NT  = (MROWS == 128) ? 8 : 4;
    constexpr int STG = MROWS * ASTRIDE + 32 * BSTRIDE;
    extern __shared__ float smem[];
    const int tid = threadIdx.x;
    const int bm = blockIdx.y * MROWS;

    const float* Wb = W;
    float* out = outA;
    const float* bias = bias0;
    if (gridDim.x == 2 && blockIdx.x == 1) {
        Wb = W + 128 * 128;
        out = outB;
        bias = nullptr;
    }

    const int lane = tid & 31, wid = tid >> 5;
    const int wm = (MROWS == 128) ? (wid >> 1) * 32 : (wid >> 2) * 32;
    const int wn = (MROWS == 128) ? (wid & 1) * 64  : (wid & 3) * 32;
    const int fr = lane >> 2, fc = lane & 3;

    float fs[4] = {1.f, 1.f, 1.f, 1.f};
    if (icvec) {
        int r = bm + wm + fr;
        fs[0] = icvec[r];      fs[1] = icvec[r + 8];
        fs[2] = icvec[r + 16]; fs[3] = icvec[r + 24];
    }

    float acc[2][NT][4];
    #pragma unroll
    for (int mt = 0; mt < 2; mt++)
        #pragma unroll
        for (int nt = 0; nt < NT; nt++)
            #pragma unroll
            for (int j = 0; j < 4; j++) acc[mt][nt][j] = 0.f;

    auto loadStage = [&](int it, int stage) {
        int k0 = it * 32;
        const float* sp = srcs.s[(k0 >> 7) & 3];
        int kloc = k0 & 127;
        float* As = smem + stage * STG;
        float* Bs = As + MROWS * ASTRIDE;
        #pragma unroll
        for (int i = 0; i < MROWS / 32; i++) {
            int id = tid + 256 * i;
            int arow = id >> 3, c4 = id & 7;
            bool p = (bm + arow) < M;
            cpasync16(As + arow * ASTRIDE + c4 * 4,
                      sp + (size_t)(bm + arow) * 128 + kloc + c4 * 4, p);
        }
        #pragma unroll
        for (int i = 0; i < 4; i++) {
            int id = tid + 256 * i;
            int krow = id >> 5, c4 = id & 31;
            cpasync16(Bs + krow * BSTRIDE + c4 * 4,
                      Wb + (size_t)(k0 + krow) * 128 + c4 * 4, true);
        }
        asm volatile("cp.async.commit_group;" ::: "memory");
    };

    loadStage(0, 0);
    for (int it = 0; it < nIter; ++it) {
        int cur = it & 1;
        if (it + 1 < nIter) {
            loadStage(it + 1, cur ^ 1);
            asm volatile("cp.async.wait_group 1;" ::: "memory");
        } else {
            asm volatile("cp.async.wait_group 0;" ::: "memory");
        }
        __syncthreads();

        const float* As = smem + cur * STG;
        const float* Bs = As + MROWS * ASTRIDE;
        bool ms = (((it * 32) >> 7) == meanSeg);
        if (ms) mma_block<NT, true >(As, Bs, acc, wm, wn, fr, fc, fs);
        else    mma_block<NT, false>(As, Bs, acc, wm, wn, fr, fc, fs);
        __syncthreads();
    }

    #pragma unroll
    for (int mt = 0; mt < 2; mt++) {
        #pragma unroll
        for (int nt = 0; nt < NT; nt++) {
            int r0 = bm + wm + mt * 16 + fr;
            int cc = wn + nt * 8 + 2 * fc;
            float b0 = 0.f, b1 = 0.f;
            if (bias) { b0 = bias[cc]; b1 = bias[cc + 1]; }
            float v0 = acc[mt][nt][0] + b0, v1 = acc[mt][nt][1] + b1;
            float v2 = acc[mt][nt][2] + b0, v3 = acc[mt][nt][3] + b1;
            if (relu) {
                v0 = fmaxf(v0, 0.f); v1 = fmaxf(v1, 0.f);
                v2 = fmaxf(v2, 0.f); v3 = fmaxf(v3, 0.f);
            }
            if (r0 < M) {
                float2 o = make_float2(v0, v1);
                *(float2*)(out + (size_t)r0 * 128 + cc) = o;
            }
            if (r0 + 8 < M) {
                float2 o = make_float2(v2, v3);
                *(float2*)(out + (size_t)(r0 + 8) * 128 + cc) = o;
            }
        }
    }
}

#define SMEM128_BYTES ((128 * ASTRIDE + 32 * BSTRIDE) * 2 * 4)
#define SMEM64_BYTES  ((64  * ASTRIDE + 32 * BSTRIDE) * 2 * 4)

// ---------------- TF32 MMA output projection: out = H2 @ Wo + b -------------
#define OAST 132
#define OBST 44
#define OSMEM_F (128 * OAST + 128 * OBST)
#define OSMEM_BYTES (OSMEM_F * 4)

__global__ __launch_bounds__(256, 2)
void out_gemm(const float* __restrict__ H2, const float* __restrict__ Wo,
              const float* __restrict__ bias, float* __restrict__ out, int M) {
    extern __shared__ float smem[];
    float* As = smem;
    float* Bs = smem + 128 * OAST;
    const int tid = threadIdx.x;
    const int bm = blockIdx.x * 128;
    const int lane = tid & 31, wid = tid >> 5;
    const int fr = lane >> 2, fc = lane & 3;

    #pragma unroll
    for (int i = 0; i < 16; i++) {
        int id = tid + 256 * i;
        int arow = id >> 5, c4 = id & 31;
        bool p = (bm + arow) < M;
        cpasync16(As + arow * OAST + c4 * 4,
                  H2 + (size_t)(bm + arow) * 128 + c4 * 4, p);
    }
    #pragma unroll
    for (int i = 0; i < 5; i++) {
        int id = tid + 256 * i;
        int wrow = id / 10, c4 = id % 10;
        cpasync16(Bs + wrow * OBST + c4 * 4,
                  Wo + (size_t)wrow * CLS + c4 * 4, true);
    }
    asm volatile("cp.async.commit_group;" ::: "memory");
    asm volatile("cp.async.wait_group 0;" ::: "memory");
    __syncthreads();

    const int m0 = wid * 16;
    float acc[5][4];
    #pragma unroll
    for (int nt = 0; nt < 5; nt++)
        #pragma unroll
        for (int j = 0; j < 4; j++) acc[nt][j] = 0.f;

    #pragma unroll
    for (int kk = 0; kk < 128; kk += 8) {
        unsigned af[4];
        af[0] = tf32u(As[(m0 + fr)     * OAST + kk + fc]);
        af[1] = tf32u(As[(m0 + fr + 8) * OAST + kk + fc]);
        af[2] = tf32u(As[(m0 + fr)     * OAST + kk + fc + 4]);
        af[3] = tf32u(As[(m0 + fr + 8) * OAST + kk + fc + 4]);
        #pragma unroll
        for (int nt = 0; nt < 5; nt++) {
            int n0 = nt * 8;
            unsigned b0 = __float_as_uint(Bs[(kk + fc)     * OBST + n0 + fr]);
            unsigned b1 = __float_as_uint(Bs[(kk + 4 + fc) * OBST + n0 + fr]);
            mma_tf32(acc[nt], af, b0, b1);
        }
    }

    #pragma unroll
    for (int nt = 0; nt < 5; nt++) {
        int r0 = bm + m0 + fr;
        int cc = nt * 8 + 2 * fc;
        float b0 = bias[cc], b1 = bias[cc + 1];
        if (r0 < M) {
            float2 o = make_float2(acc[nt][0] + b0, acc[nt][1] + b1);
            *(float2*)(out + (size_t)r0 * CLS + cc) = o;
        }
        if (r0 + 8 < M) {
            float2 o = make_float2(acc[nt][2] + b0, acc[nt][3] + b1);
            *(float2*)(out + (size_t)(r0 + 8) * CLS + cc) = o;
        }
    }
}

// ---------------- host side -------------------------------------------------
extern "C" void kernel_launch(void* const* d_in, const int* in_sizes, int n_in,
                              void* d_out, int out_size) {
    const float* x      = (const float*)d_in[0];
    const int*   ei     = (const int*)  d_in[1];
    const float* w1_pre = (const float*)d_in[2];
    const float* b1_pre = (const float*)d_in[3];
    const float* w1_post= (const float*)d_in[4];
    const float* b1_post= (const float*)d_in[5];
    const float* w1_lin = (const float*)d_in[6];
    const float* b1_lin = (const float*)d_in[7];
    const float* w2_pre = (const float*)d_in[8];
    const float* b2_pre = (const float*)d_in[9];
    const float* w2_post= (const float*)d_in[10];
    const float* b2_post= (const float*)d_in[11];
    const float* w2_lin = (const float*)d_in[12];
    const float* b2_lin = (const float*)d_in[13];
    const float* w_out  = (const float*)d_in[14];
    const float* b_out  = (const float*)d_in[15];
    float* out = (float*)d_out;

    static int init_done = 0;
    static cudaStream_t side = nullptr;
    static cudaEvent_t evFork = nullptr, evJoin = nullptr;
    if (!init_done) {
        cudaFuncSetAttribute(mma_gemm<128>, cudaFuncAttributeMaxDynamicSharedMemorySize,
                             SMEM128_BYTES);
        cudaFuncSetAttribute(mma_gemm<64>, cudaFuncAttributeMaxDynamicSharedMemorySize,
                             SMEM64_BYTES);
        cudaFuncSetAttribute(out_gemm, cudaFuncAttributeMaxDynamicSharedMemorySize,
                             OSMEM_BYTES);
        cudaStreamCreateWithFlags(&side, cudaStreamNonBlocking);
        cudaEventCreateWithFlags(&evFork, cudaEventDisableTiming);
        cudaEventCreateWithFlags(&evJoin, cudaEventDisableTiming);
        init_done = 1;
    }

    void *pA, *pB, *pH, *pH2, *pS, *pM, *pIC, *pWf1, *pWf2, *pWpreR, *pWoR,
         *pHist, *pCur;
    cudaGetSymbolAddress(&pA, g_A);
    cudaGetSymbolAddress(&pB, g_B);
    cudaGetSymbolAddress(&pH, g_H);
    cudaGetSymbolAddress(&pH2, g_H2);
    cudaGetSymbolAddress(&pS, g_S);
    cudaGetSymbolAddress(&pM, g_M);
    cudaGetSymbolAddress(&pIC, g_IC);
    cudaGetSymbolAddress(&pWf1, g_Wf1);
    cudaGetSymbolAddress(&pWf2, g_Wf2);
    cudaGetSymbolAddress(&pWpreR, g_WpreR);
    cudaGetSymbolAddress(&pWoR, g_WoR);
    cudaGetSymbolAddress(&pHist, g_hist);
    cudaGetSymbolAddress(&pCur, g_cur);

    const int* srcp = ei;           // edge_index[0]
    const int* dstp = ei + NEDGES;  // edge_index[1]

    // ---- fork: preproc + BOTH fuse kernels on side stream -------------------
    // (all depend only on inputs; overlap with cvt + layer-1 pre-GEMM)
    cudaEventRecord(evFork, 0);
    cudaStreamWaitEvent(side, evFork, 0);
    cudaMemsetAsync(pHist, 0, NNODES * sizeof(int), side);
    cudaMemsetAsync(pCur,  0, NNODES * sizeof(int), side);
    hist_kernel<<<(NEDGES + 255) / 256, 256, 0, side>>>(dstp);
    scan_kernel<<<1, 1024, 0, side>>>();
    scatter_kernel<<<(NEDGES + 255) / 256, 256, 0, side>>>(srcp, dstp);
    fuse_kernel<<<513, 128, 0, side>>>(w1_post, b1_post, w1_lin, b1_lin, (float*)pWf1);
    fuse_kernel<<<513, 128, 0, side>>>(w2_post, b2_post, w2_lin, b2_lin, (float*)pWf2);
    cudaEventRecord(evJoin, side);

    // ---- main stream: weights + layer-1 pre-GEMM (edge-independent) --------
    const int cvt_total = CVT_N1 + CVT_N2 + CVT_N3;
    cvt_all_kernel<<<(cvt_total + 255) / 256, 256>>>(w1_pre, w2_pre, w_out);

    const int MB128 = (NNODES + 127) / 128;
    const int MB64  = (NNODES + 63) / 64;
    GemmSrcs pre1; pre1.s[0] = x; pre1.s[1] = x; pre1.s[2] = x; pre1.s[3] = x;
    mma_gemm<128><<<dim3(2, MB128), 256, SMEM128_BYTES>>>(
        pre1, (const float*)pWpreR, b1_pre, (float*)pA, (float*)pB,
        nullptr, -1, NNODES, 128 / 32, 0);

    // ---- join: aggregation needs sorted edges (fuses also done) ------------
    cudaStreamWaitEvent(0, evJoin, 0);
    aggregate_kernel<<<(NNODES + 7) / 8, 256>>>();

    GemmSrcs cat1; cat1.s[0] = x; cat1.s[1] = (const float*)pS;
    cat1.s[2] = (const float*)pM; cat1.s[3] = (const float*)pS;
    mma_gemm<64><<<dim3(1, MB64), 256, SMEM64_BYTES>>>(
        cat1, (const float*)pWf1, (const float*)pWf1 + 512 * FDIM,
        (float*)pH, (float*)pH, (const float*)pIC, 1, NNODES, 512 / 32, 1);

    // ---- layer 2 -----------------------------------------------------------
    GemmSrcs pre2; pre2.s[0] = (const float*)pH; pre2.s[1] = pre2.s[0];
    pre2.s[2] = pre2.s[0]; pre2.s[3] = pre2.s[0];
    mma_gemm<128><<<dim3(2, MB128), 256, SMEM128_BYTES>>>(
        pre2, (const float*)pWpreR + 256 * FDIM, b2_pre, (float*)pA, (float*)pB,
        nullptr, -1, NNODES, 128 / 32, 0);
    aggregate_kernel<<<(NNODES + 7) / 8, 256>>>();

    GemmSrcs cat2; cat2.s[0] = (const float*)pH; cat2.s[1] = (const float*)pS;
    cat2.s[2] = (const float*)pM; cat2.s[3] = (const float*)pS;
    mma_gemm<64><<<dim3(1, MB64), 256, SMEM64_BYTES>>>(
        cat2, (const float*)pWf2, (const float*)pWf2 + 512 * FDIM,
        (float*)pH2, (float*)pH2, (const float*)pIC, 1, NNODES, 512 / 32, 1);

    // ---- output projection (TF32 MMA) --------------------------------------
    out_gemm<<<(NNODES + 127) / 128, 256, OSMEM_BYTES>>>(
        (const float*)pH2, (const float*)pWoR, b_out, out, NNODES);
}

// round 9
// speedup vs baseline: 1.0007x; 1.0007x over previous
#include <cuda_runtime.h>
#include <math.h>
#include <stdint.h>

#define NNODES 50000
#define NEDGES 500000
#define FDIM   128
#define CLS    40

// ---------------- scratch (static device globals; no allocation) ------------
__device__ float g_A   [NNODES * FDIM];   // A' = x @ W_top + b_pre (fp32)
__device__ float g_B   [NNODES * FDIM];   // B  = x @ W_bot        (fp32)
__device__ float g_S   [NNODES * FDIM];   // SUM aggregator  (fp32)
__device__ float g_M   [NNODES * FDIM];   // MAX aggregator  (fp32)
__device__ float g_H   [NNODES * FDIM];   // hidden after layer 1 (fp32)
__device__ float g_H2  [NNODES * FDIM];   // hidden after layer 2 (fp32)
__device__ float g_IC  [NNODES + 128];    // 1/max(cnt,1) per node (padded)
__device__ float g_Wf1 [513 * FDIM];      // fused W' layer 1 (+bias row, fp32)
__device__ float g_Wf2 [513 * FDIM];      // fused W' layer 2 (+bias row, fp32)
__device__ float g_WpreR[2 * 256 * FDIM]; // tf32-rounded w1_pre, w2_pre
__device__ float g_WoR [FDIM * CLS];      // tf32-rounded w_out
__device__ int   g_hist[NNODES];
__device__ int   g_off [NNODES + 1];
__device__ int   g_cur [NNODES];
__device__ int   g_ssrc[NEDGES];          // src ids grouped (counting-sorted) by dst

// ---------------- helpers ---------------------------------------------------
__device__ __forceinline__ float tf32r(float x) {
    unsigned u;
    asm("cvt.rna.tf32.f32 %0, %1;" : "=r"(u) : "f"(x));
    return __uint_as_float(u);
}

__device__ __forceinline__ unsigned tf32u(float x) {
    unsigned u;
    asm("cvt.rna.tf32.f32 %0, %1;" : "=r"(u) : "f"(x));
    return u;
}

__device__ __forceinline__ void cpasync16(void* dst, const void* src, bool pred) {
    unsigned sa = (unsigned)__cvta_generic_to_shared(dst);
    int sz = pred ? 16 : 0;
    asm volatile("cp.async.cg.shared.global [%0], [%1], 16, %2;\n"
                 :: "r"(sa), "l"(src), "r"(sz));
}

__device__ __forceinline__ void mma_tf32(float* c, const unsigned* a,
                                         unsigned b0, unsigned b1) {
    asm volatile(
        "mma.sync.aligned.m16n8k8.row.col.f32.tf32.tf32.f32 "
        "{%0,%1,%2,%3}, {%4,%5,%6,%7}, {%8,%9}, {%0,%1,%2,%3};"
        : "+f"(c[0]), "+f"(c[1]), "+f"(c[2]), "+f"(c[3])
        : "r"(a[0]), "r"(a[1]), "r"(a[2]), "r"(a[3]), "r"(b0), "r"(b1));
}

// ---------------- graph preprocessing ---------------------------------------
__global__ void hist_kernel(const int* __restrict__ dst) {
    int i = blockIdx.x * blockDim.x + threadIdx.x;
    if (i < NEDGES) atomicAdd(&g_hist[dst[i]], 1);
}

__global__ void scan_kernel() {  // 1 block, 1024 threads
    __shared__ int s[1024];
    const int t = threadIdx.x;
    const int chunk = (NNODES + 1023) / 1024;
    int beg = t * chunk;
    int end = beg + chunk; if (end > NNODES) end = NNODES;
    int sum = 0;
    for (int i = beg; i < end; i++) sum += g_hist[i];
    s[t] = sum;
    __syncthreads();
    for (int d = 1; d < 1024; d <<= 1) {
        int v = (t >= d) ? s[t - d] : 0;
        __syncthreads();
        s[t] += v;
        __syncthreads();
    }
    int run = (t > 0) ? s[t - 1] : 0;
    for (int i = beg; i < end; i++) { g_off[i] = run; run += g_hist[i]; }
    if (t == 0) g_off[NNODES] = NEDGES;
}

__global__ void scatter_kernel(const int* __restrict__ src, const int* __restrict__ dst) {
    int i = blockIdx.x * blockDim.x + threadIdx.x;
    if (i >= NEDGES) return;
    int d = dst[i];
    int p = g_off[d] + atomicAdd(&g_cur[d], 1);
    g_ssrc[p] = src[i];
}

// tf32-round all weight matrices in a single launch
#define CVT_N1 (256 * FDIM)
#define CVT_N2 (256 * FDIM)
#define CVT_N3 (FDIM * CLS)
__global__ void cvt_all_kernel(const float* __restrict__ w1,
                               const float* __restrict__ w2,
                               const float* __restrict__ wo) {
    int i = blockIdx.x * blockDim.x + threadIdx.x;
    if (i < CVT_N1) g_WpreR[i] = tf32r(w1[i]);
    else if (i < CVT_N1 + CVT_N2) g_WpreR[i] = tf32r(w2[i - CVT_N1]);
    else if (i < CVT_N1 + CVT_N2 + CVT_N3) g_WoR[i - CVT_N1 - CVT_N2] =
        tf32r(wo[i - CVT_N1 - CVT_N2]);
}

// ---------------- aggregation (warp/node, float4 lanes, unroll 4) ------------
__global__ void aggregate_kernel() {
    int node = (blockIdx.x * blockDim.x + threadIdx.x) >> 5;
    if (node >= NNODES) return;
    int lane = threadIdx.x & 31;
    int beg = g_off[node], end = g_off[node + 1];
    const float4* Bv = (const float4*)g_B;
    float4 s = make_float4(0.f, 0.f, 0.f, 0.f);
    float4 m = make_float4(-3.4e38f, -3.4e38f, -3.4e38f, -3.4e38f);
    int e = beg;
    for (; e + 3 < end; e += 4) {
        int sv0 = __ldg(&g_ssrc[e]);
        int sv1 = __ldg(&g_ssrc[e + 1]);
        int sv2 = __ldg(&g_ssrc[e + 2]);
        int sv3 = __ldg(&g_ssrc[e + 3]);
        float4 v0 = __ldg(&Bv[(size_t)sv0 * 32 + lane]);
        float4 v1 = __ldg(&Bv[(size_t)sv1 * 32 + lane]);
        float4 v2 = __ldg(&Bv[(size_t)sv2 * 32 + lane]);
        float4 v3 = __ldg(&Bv[(size_t)sv3 * 32 + lane]);
        s.x += (v0.x + v1.x) + (v2.x + v3.x);
        s.y += (v0.y + v1.y) + (v2.y + v3.y);
        s.z += (v0.z + v1.z) + (v2.z + v3.z);
        s.w += (v0.w + v1.w) + (v2.w + v3.w);
        m.x = fmaxf(m.x, fmaxf(fmaxf(v0.x, v1.x), fmaxf(v2.x, v3.x)));
        m.y = fmaxf(m.y, fmaxf(fmaxf(v0.y, v1.y), fmaxf(v2.y, v3.y)));
        m.z = fmaxf(m.z, fmaxf(fmaxf(v0.z, v1.z), fmaxf(v2.z, v3.z)));
        m.w = fmaxf(m.w, fmaxf(fmaxf(v0.w, v1.w), fmaxf(v2.w, v3.w)));
    }
    for (; e < end; e++) {
        int sv = __ldg(&g_ssrc[e]);
        float4 v = __ldg(&Bv[(size_t)sv * 32 + lane]);
        s.x += v.x; s.y += v.y; s.z += v.z; s.w += v.w;
        m.x = fmaxf(m.x, v.x); m.y = fmaxf(m.y, v.y);
        m.z = fmaxf(m.z, v.z); m.w = fmaxf(m.w, v.w);
    }
    size_t o = (size_t)node * 32 + lane;
    float c = (float)(end - beg);
    float ic = 1.f / fmaxf(c, 1.f);
    if (lane == 0) g_IC[node] = ic;
    float4 a = ((const float4*)g_A)[o];
    float4 t;
    t.x = fmaf(c, a.x, s.x); t.y = fmaf(c, a.y, s.y);
    t.z = fmaf(c, a.z, s.z); t.w = fmaf(c, a.w, s.w);
    ((float4*)g_S)[o] = t;
    bool nz = (c > 0.f);
    float4 mx;
    mx.x = nz ? (a.x + m.x) : 0.f; mx.y = nz ? (a.y + m.y) : 0.f;
    mx.z = nz ? (a.z + m.z) : 0.f; mx.w = nz ? (a.w + m.w) : 0.f;
    ((float4*)g_M)[o] = mx;
}

// ---------------- W' = [w_post; b_post] @ w_lin (+ b_lin on bias row) -------
__global__ void fuse_kernel(const float* __restrict__ wpost, const float* __restrict__ bpost,
                            const float* __restrict__ wlin,  const float* __restrict__ blin,
                            float* __restrict__ wf) {
    __shared__ float srow[FDIM];
    int r = blockIdx.x;    // 0..512
    int c = threadIdx.x;   // 0..127
    const float* row = (r < 512) ? (wpost + (size_t)r * FDIM) : bpost;
    srow[c] = row[c];
    __syncthreads();
    float acc = (r == 512) ? blin[c] : 0.f;
    #pragma unroll 8
    for (int k = 0; k < FDIM; k++) acc = fmaf(srow[k], wlin[k * FDIM + c], acc);
    wf[r * FDIM + c] = (r < 512) ? tf32r(acc) : acc;  // bias row stays fp32
}

// ---------------- TF32 tensor-core GEMM (templated M tile) -------------------
// MROWS=128: 8 warps 4(M)x2(N), warp tile 32x64 (NT=8). Used for pre-GEMMs
//   (gridDim.x==2 selects weight half + output; dual-output trick).
// MROWS=64 : 8 warps 2(M)x4(N), warp tile 32x32 (NT=4). Used for cat-GEMMs:
//   halves block M so grid 782 -> ~2.64 rounds of half-cost blocks instead of
//   2 rounds with a 34% idle tail. A traffic unchanged; only tiny W re-read.
// SCALE variant applies per-row ic to the mean segment only (compiled out
// elsewhere). Per-output accumulation order identical for both MROWS.
#define ASTRIDE 36
#define BSTRIDE 136

struct GemmSrcs { const float* s[4]; };

template<int NT, bool SCALE>
__device__ __forceinline__ void mma_block(const float* __restrict__ As,
                                          const float* __restrict__ Bs,
                                          float (*acc)[NT][4],
                                          int wm, int wn, int fr, int fc,
                                          const float* fs) {
    #pragma unroll
    for (int kk = 0; kk < 32; kk += 8) {
        float v0 = As[(wm + fr)      * ASTRIDE + kk + fc];
        float v1 = As[(wm + fr + 8)  * ASTRIDE + kk + fc];
        float v2 = As[(wm + fr)      * ASTRIDE + kk + fc + 4];
        float v3 = As[(wm + fr + 8)  * ASTRIDE + kk + fc + 4];
        float v4 = As[(wm + fr + 16) * ASTRIDE + kk + fc];
        float v5 = As[(wm + fr + 24) * ASTRIDE + kk + fc];
        float v6 = As[(wm + fr + 16) * ASTRIDE + kk + fc + 4];
        float v7 = As[(wm + fr + 24) * ASTRIDE + kk + fc + 4];
        if (SCALE) {
            v0 *= fs[0]; v1 *= fs[1]; v2 *= fs[0]; v3 *= fs[1];
            v4 *= fs[2]; v5 *= fs[3]; v6 *= fs[2]; v7 *= fs[3];
        }
        unsigned af0[4] = {tf32u(v0), tf32u(v1), tf32u(v2), tf32u(v3)};
        unsigned af1[4] = {tf32u(v4), tf32u(v5), tf32u(v6), tf32u(v7)};
        #pragma unroll
        for (int nt = 0; nt < NT; nt++) {
            int n0 = wn + nt * 8;
            unsigned b0 = __float_as_uint(Bs[(kk + fc)     * BSTRIDE + n0 + fr]);
            unsigned b1 = __float_as_uint(Bs[(kk + 4 + fc) * BSTRIDE + n0 + fr]);
            mma_tf32(acc[0][nt], af0, b0, b1);
            mma_tf32(acc[1][nt], af1, b0, b1);
        }
    }
}

template<int MROWS>
__global__ __launch_bounds__(256, 2)
void mma_gemm(GemmSrcs srcs, const float* __restrict__ W,
              const float* __restrict__ bias0,
              float* outA, float* outB,
              const float* __restrict__ icvec, int meanSeg,
              int M, int nIter, int relu) {
    constexpr int NT  = (MROWS == 128) ? 8 : 4;
    constexpr int STG = MROWS * ASTRIDE + 32 * BSTRIDE;
    extern __shared__ float smem[];
    const int tid = threadIdx.x;
    const int bm = blockIdx.y * MROWS;

    const float* Wb = W;
    float* out = outA;
    const float* bias = bias0;
    if (gridDim.x == 2 && blockIdx.x == 1) {
        Wb = W + 128 * 128;
        out = outB;
        bias = nullptr;
    }

    const int lane = tid & 31, wid = tid >> 5;
    const int wm = (MROWS == 128) ? (wid >> 1) * 32 : (wid >> 2) * 32;
    const int wn = (MROWS == 128) ? (wid & 1) * 64  : (wid & 3) * 32;
    const int fr = lane >> 2, fc = lane & 3;

    float fs[4] = {1.f, 1.f, 1.f, 1.f};
    if (icvec) {
        int r = bm + wm + fr;
        fs[0] = icvec[r];      fs[1] = icvec[r + 8];
        fs[2] = icvec[r + 16]; fs[3] = icvec[r + 24];
    }

    float acc[2][NT][4];
    #pragma unroll
    for (int mt = 0; mt < 2; mt++)
        #pragma unroll
        for (int nt = 0; nt < NT; nt++)
            #pragma unroll
            for (int j = 0; j < 4; j++) acc[mt][nt][j] = 0.f;

    auto loadStage = [&](int it, int stage) {
        int k0 = it * 32;
        const float* sp = srcs.s[(k0 >> 7) & 3];
        int kloc = k0 & 127;
        float* As = smem + stage * STG;
        float* Bs = As + MROWS * ASTRIDE;
        #pragma unroll
        for (int i = 0; i < MROWS / 32; i++) {
            int id = tid + 256 * i;
            int arow = id >> 3, c4 = id & 7;
            bool p = (bm + arow) < M;
            cpasync16(As + arow * ASTRIDE + c4 * 4,
                      sp + (size_t)(bm + arow) * 128 + kloc + c4 * 4, p);
        }
        #pragma unroll
        for (int i = 0; i < 4; i++) {
            int id = tid + 256 * i;
            int krow = id >> 5, c4 = id & 31;
            cpasync16(Bs + krow * BSTRIDE + c4 * 4,
                      Wb + (size_t)(k0 + krow) * 128 + c4 * 4, true);
        }
        asm volatile("cp.async.commit_group;" ::: "memory");
    };

    loadStage(0, 0);
    for (int it = 0; it < nIter; ++it) {
        int cur = it & 1;
        if (it + 1 < nIter) {
            loadStage(it + 1, cur ^ 1);
            asm volatile("cp.async.wait_group 1;" ::: "memory");
        } else {
            asm volatile("cp.async.wait_group 0;" ::: "memory");
        }
        __syncthreads();

        const float* As = smem + cur * STG;
        const float* Bs = As + MROWS * ASTRIDE;
        bool ms = (((it * 32) >> 7) == meanSeg);
        if (ms) mma_block<NT, true >(As, Bs, acc, wm, wn, fr, fc, fs);
        else    mma_block<NT, false>(As, Bs, acc, wm, wn, fr, fc, fs);
        __syncthreads();
    }

    #pragma unroll
    for (int mt = 0; mt < 2; mt++) {
        #pragma unroll
        for (int nt = 0; nt < NT; nt++) {
            int r0 = bm + wm + mt * 16 + fr;
            int cc = wn + nt * 8 + 2 * fc;
            float b0 = 0.f, b1 = 0.f;
            if (bias) { b0 = bias[cc]; b1 = bias[cc + 1]; }
            float v0 = acc[mt][nt][0] + b0, v1 = acc[mt][nt][1] + b1;
            float v2 = acc[mt][nt][2] + b0, v3 = acc[mt][nt][3] + b1;
            if (relu) {
                v0 = fmaxf(v0, 0.f); v1 = fmaxf(v1, 0.f);
                v2 = fmaxf(v2, 0.f); v3 = fmaxf(v3, 0.f);
            }
            if (r0 < M) {
                float2 o = make_float2(v0, v1);
                *(float2*)(out + (size_t)r0 * 128 + cc) = o;
            }
            if (r0 + 8 < M) {
                float2 o = make_float2(v2, v3);
                *(float2*)(out + (size_t)(r0 + 8) * 128 + cc) = o;
            }
        }
    }
}

#define SMEM128_BYTES ((128 * ASTRIDE + 32 * BSTRIDE) * 2 * 4)
#define SMEM64_BYTES  ((64  * ASTRIDE + 32 * BSTRIDE) * 2 * 4)

// ---------------- TF32 MMA output projection: out = H2 @ Wo + b -------------
#define OAST 132
#define OBST 44
#define OSMEM_F (128 * OAST + 128 * OBST)
#define OSMEM_BYTES (OSMEM_F * 4)

__global__ __launch_bounds__(256, 2)
void out_gemm(const float* __restrict__ H2, const float* __restrict__ Wo,
              const float* __restrict__ bias, float* __restrict__ out, int M) {
    extern __shared__ float smem[];
    float* As = smem;
    float* Bs = smem + 128 * OAST;
    const int tid = threadIdx.x;
    const int bm = blockIdx.x * 128;
    const int lane = tid & 31, wid = tid >> 5;
    const int fr = lane >> 2, fc = lane & 3;

    #pragma unroll
    for (int i = 0; i < 16; i++) {
        int id = tid + 256 * i;
        int arow = id >> 5, c4 = id & 31;
        bool p = (bm + arow) < M;
        cpasync16(As + arow * OAST + c4 * 4,
                  H2 + (size_t)(bm + arow) * 128 + c4 * 4, p);
    }
    #pragma unroll
    for (int i = 0; i < 5; i++) {
        int id = tid + 256 * i;
        int wrow = id / 10, c4 = id % 10;
        cpasync16(Bs + wrow * OBST + c4 * 4,
                  Wo + (size_t)wrow * CLS + c4 * 4, true);
    }
    asm volatile("cp.async.commit_group;" ::: "memory");
    asm volatile("cp.async.wait_group 0;" ::: "memory");
    __syncthreads();

    const int m0 = wid * 16;
    float acc[5][4];
    #pragma unroll
    for (int nt = 0; nt < 5; nt++)
        #pragma unroll
        for (int j = 0; j < 4; j++) acc[nt][j] = 0.f;

    #pragma unroll
    for (int kk = 0; kk < 128; kk += 8) {
        unsigned af[4];
        af[0] = tf32u(As[(m0 + fr)     * OAST + kk + fc]);
        af[1] = tf32u(As[(m0 + fr + 8) * OAST + kk + fc]);
        af[2] = tf32u(As[(m0 + fr)     * OAST + kk + fc + 4]);
        af[3] = tf32u(As[(m0 + fr + 8) * OAST + kk + fc + 4]);
        #pragma unroll
        for (int nt = 0; nt < 5; nt++) {
            int n0 = nt * 8;
            unsigned b0 = __float_as_uint(Bs[(kk + fc)     * OBST + n0 + fr]);
            unsigned b1 = __float_as_uint(Bs[(kk + 4 + fc) * OBST + n0 + fr]);
            mma_tf32(acc[nt], af, b0, b1);
        }
    }

    #pragma unroll
    for (int nt = 0; nt < 5; nt++) {
        int r0 = bm + m0 + fr;
        int cc = nt * 8 + 2 * fc;
        float b0 = bias[cc], b1 = bias[cc + 1];
        if (r0 < M) {
            float2 o = make_float2(acc[nt][0] + b0, acc[nt][1] + b1);
            *(float2*)(out + (size_t)r0 * CLS + cc) = o;
        }
        if (r0 + 8 < M) {
            float2 o = make_float2(acc[nt][2] + b0, acc[nt][3] + b1);
            *(float2*)(out + (size_t)(r0 + 8) * CLS + cc) = o;
        }
    }
}

// ---------------- host side -------------------------------------------------
extern "C" void kernel_launch(void* const* d_in, const int* in_sizes, int n_in,
                              void* d_out, int out_size) {
    const float* x      = (const float*)d_in[0];
    const int*   ei     = (const int*)  d_in[1];
    const float* w1_pre = (const float*)d_in[2];
    const float* b1_pre = (const float*)d_in[3];
    const float* w1_post= (const float*)d_in[4];
    const float* b1_post= (const float*)d_in[5];
    const float* w1_lin = (const float*)d_in[6];
    const float* b1_lin = (const float*)d_in[7];
    const float* w2_pre = (const float*)d_in[8];
    const float* b2_pre = (const float*)d_in[9];
    const float* w2_post= (const float*)d_in[10];
    const float* b2_post= (const float*)d_in[11];
    const float* w2_lin = (const float*)d_in[12];
    const float* b2_lin = (const float*)d_in[13];
    const float* w_out  = (const float*)d_in[14];
    const float* b_out  = (const float*)d_in[15];
    float* out = (float*)d_out;

    static int init_done = 0;
    static cudaStream_t side = nullptr;
    static cudaEvent_t evFork = nullptr, evJoin = nullptr;
    if (!init_done) {
        cudaFuncSetAttribute(mma_gemm<128>, cudaFuncAttributeMaxDynamicSharedMemorySize,
                             SMEM128_BYTES);
        cudaFuncSetAttribute(mma_gemm<64>, cudaFuncAttributeMaxDynamicSharedMemorySize,
                             SMEM64_BYTES);
        cudaFuncSetAttribute(out_gemm, cudaFuncAttributeMaxDynamicSharedMemorySize,
                             OSMEM_BYTES);
        cudaStreamCreateWithFlags(&side, cudaStreamNonBlocking);
        cudaEventCreateWithFlags(&evFork, cudaEventDisableTiming);
        cudaEventCreateWithFlags(&evJoin, cudaEventDisableTiming);
        init_done = 1;
    }

    void *pA, *pB, *pH, *pH2, *pS, *pM, *pIC, *pWf1, *pWf2, *pWpreR, *pWoR,
         *pHist, *pCur;
    cudaGetSymbolAddress(&pA, g_A);
    cudaGetSymbolAddress(&pB, g_B);
    cudaGetSymbolAddress(&pH, g_H);
    cudaGetSymbolAddress(&pH2, g_H2);
    cudaGetSymbolAddress(&pS, g_S);
    cudaGetSymbolAddress(&pM, g_M);
    cudaGetSymbolAddress(&pIC, g_IC);
    cudaGetSymbolAddress(&pWf1, g_Wf1);
    cudaGetSymbolAddress(&pWf2, g_Wf2);
    cudaGetSymbolAddress(&pWpreR, g_WpreR);
    cudaGetSymbolAddress(&pWoR, g_WoR);
    cudaGetSymbolAddress(&pHist, g_hist);
    cudaGetSymbolAddress(&pCur, g_cur);

    const int* srcp = ei;           // edge_index[0]
    const int* dstp = ei + NEDGES;  // edge_index[1]

    // ---- fork: preproc + BOTH fuse kernels on side stream -------------------
    // (all depend only on inputs; overlap with cvt + layer-1 pre-GEMM)
    cudaEventRecord(evFork, 0);
    cudaStreamWaitEvent(side, evFork, 0);
    cudaMemsetAsync(pHist, 0, NNODES * sizeof(int), side);
    cudaMemsetAsync(pCur,  0, NNODES * sizeof(int), side);
    hist_kernel<<<(NEDGES + 255) / 256, 256, 0, side>>>(dstp);
    scan_kernel<<<1, 1024, 0, side>>>();
    scatter_kernel<<<(NEDGES + 255) / 256, 256, 0, side>>>(srcp, dstp);
    fuse_kernel<<<513, 128, 0, side>>>(w1_post, b1_post, w1_lin, b1_lin, (float*)pWf1);
    fuse_kernel<<<513, 128, 0, side>>>(w2_post, b2_post, w2_lin, b2_lin, (float*)pWf2);
    cudaEventRecord(evJoin, side);

    // ---- main stream: weights + layer-1 pre-GEMM (edge-independent) --------
    const int cvt_total = CVT_N1 + CVT_N2 + CVT_N3;
    cvt_all_kernel<<<(cvt_total + 255) / 256, 256>>>(w1_pre, w2_pre, w_out);

    const int MB128 = (NNODES + 127) / 128;
    const int MB64  = (NNODES + 63) / 64;
    GemmSrcs pre1; pre1.s[0] = x; pre1.s[1] = x; pre1.s[2] = x; pre1.s[3] = x;
    mma_gemm<128><<<dim3(2, MB128), 256, SMEM128_BYTES>>>(
        pre1, (const float*)pWpreR, b1_pre, (float*)pA, (float*)pB,
        nullptr, -1, NNODES, 128 / 32, 0);

    // ---- join: aggregation needs sorted edges (fuses also done) ------------
    cudaStreamWaitEvent(0, evJoin, 0);
    aggregate_kernel<<<(NNODES + 7) / 8, 256>>>();

    GemmSrcs cat1; cat1.s[0] = x; cat1.s[1] = (const float*)pS;
    cat1.s[2] = (const float*)pM; cat1.s[3] = (const float*)pS;
    mma_gemm<64><<<dim3(1, MB64), 256, SMEM64_BYTES>>>(
        cat1, (const float*)pWf1, (const float*)pWf1 + 512 * FDIM,
        (float*)pH, (float*)pH, (const float*)pIC, 1, NNODES, 512 / 32, 1);

    // ---- layer 2 -----------------------------------------------------------
    GemmSrcs pre2; pre2.s[0] = (const float*)pH; pre2.s[1] = pre2.s[0];
    pre2.s[2] = pre2.s[0]; pre2.s[3] = pre2.s[0];
    mma_gemm<128><<<dim3(2, MB128), 256, SMEM128_BYTES>>>(
        pre2, (const float*)pWpreR + 256 * FDIM, b2_pre, (float*)pA, (float*)pB,
        nullptr, -1, NNODES, 128 / 32, 0);
    aggregate_kernel<<<(NNODES + 7) / 8, 256>>>();

    GemmSrcs cat2; cat2.s[0] = (const float*)pH; cat2.s[1] = (const float*)pS;
    cat2.s[2] = (const float*)pM; cat2.s[3] = (const float*)pS;
    mma_gemm<64><<<dim3(1, MB64), 256, SMEM64_BYTES>>>(
        cat2, (const float*)pWf2, (const float*)pWf2 + 512 * FDIM,
        (float*)pH2, (float*)pH2, (const float*)pIC, 1, NNODES, 512 / 32, 1);

    // ---- output projection (TF32 MMA) --------------------------------------
    out_gemm<<<(NNODES + 127) / 128, 256, OSMEM_BYTES>>>(
        (const float*)pH2, (const float*)pWoR, b_out, out, NNODES);
}

// round 10
// speedup vs baseline: 1.1562x; 1.1554x over previous
#include <cuda_runtime.h>
#include <cuda_fp16.h>
#include <math.h>
#include <stdint.h>

#define NNODES 50000
#define NEDGES 500000
#define FDIM   128
#define CLS    40

// ---------------- scratch (static device globals; no allocation) ------------
__device__ float  g_A   [NNODES * FDIM];   // A' = x @ W_top + b_pre (fp32)
__device__ float  g_B   [NNODES * FDIM];   // B  = x @ W_bot        (fp32)
__device__ float  g_S   [NNODES * FDIM];   // SUM aggregator  (fp32)
__device__ float  g_M   [NNODES * FDIM];   // MAX aggregator  (fp32)
__device__ float  g_H   [NNODES * FDIM];   // hidden after layer 1 (fp32)
__device__ float  g_H2  [NNODES * FDIM];   // hidden after layer 2 (fp32)
__device__ float  g_IC  [NNODES + 128];    // 1/max(cnt,1) per node (padded)
__device__ __half g_WpreH[2 * 2 * FDIM * FDIM]; // [layer][half][n][k] fp16 transposed
__device__ __half g_WfT1[FDIM * 512];      // fused W' layer 1, [n][k] fp16 transposed
__device__ __half g_WfT2[FDIM * 512];      // fused W' layer 2, [n][k] fp16 transposed
__device__ float  g_Wfb1[FDIM];            // fused bias layer 1 (fp32)
__device__ float  g_Wfb2[FDIM];            // fused bias layer 2 (fp32)
__device__ float  g_WoR [FDIM * CLS];      // tf32-rounded w_out (fp32)
__device__ int    g_hist[NNODES];
__device__ int    g_off [NNODES + 1];
__device__ int    g_cur [NNODES];
__device__ int    g_ssrc[NEDGES];          // src ids grouped (counting-sorted) by dst

// ---------------- helpers ---------------------------------------------------
__device__ __forceinline__ float tf32r(float x) {
    unsigned u;
    asm("cvt.rna.tf32.f32 %0, %1;" : "=r"(u) : "f"(x));
    return __uint_as_float(u);
}

__device__ __forceinline__ unsigned tf32u(float x) {
    unsigned u;
    asm("cvt.rna.tf32.f32 %0, %1;" : "=r"(u) : "f"(x));
    return u;
}

__device__ __forceinline__ unsigned pack_h2(float lo, float hi) {
    __half2 h = __floats2half2_rn(lo, hi);   // .x = lo (low 16 bits) = lower k
    return *reinterpret_cast<unsigned*>(&h);
}

__device__ __forceinline__ void cpasync16(void* dst, const void* src, bool pred) {
    unsigned sa = (unsigned)__cvta_generic_to_shared(dst);
    int sz = pred ? 16 : 0;
    asm volatile("cp.async.cg.shared.global [%0], [%1], 16, %2;\n"
                 :: "r"(sa), "l"(src), "r"(sz));
}

// fp16 MMA, fp32 accumulate: D(16x8) += A(16x16) * B(16x8)
__device__ __forceinline__ void mma_f16(float* c, const unsigned* a,
                                        unsigned b0, unsigned b1) {
    asm volatile(
        "mma.sync.aligned.m16n8k16.row.col.f32.f16.f16.f32 "
        "{%0,%1,%2,%3}, {%4,%5,%6,%7}, {%8,%9}, {%0,%1,%2,%3};"
        : "+f"(c[0]), "+f"(c[1]), "+f"(c[2]), "+f"(c[3])
        : "r"(a[0]), "r"(a[1]), "r"(a[2]), "r"(a[3]), "r"(b0), "r"(b1));
}

// tf32 MMA (kept for the small output projection)
__device__ __forceinline__ void mma_tf32(float* c, const unsigned* a,
                                         unsigned b0, unsigned b1) {
    asm volatile(
        "mma.sync.aligned.m16n8k8.row.col.f32.tf32.tf32.f32 "
        "{%0,%1,%2,%3}, {%4,%5,%6,%7}, {%8,%9}, {%0,%1,%2,%3};"
        : "+f"(c[0]), "+f"(c[1]), "+f"(c[2]), "+f"(c[3])
        : "r"(a[0]), "r"(a[1]), "r"(a[2]), "r"(a[3]), "r"(b0), "r"(b1));
}

// ---------------- graph preprocessing ---------------------------------------
__global__ void hist_kernel(const int* __restrict__ dst) {
    int i = blockIdx.x * blockDim.x + threadIdx.x;
    if (i < NEDGES) atomicAdd(&g_hist[dst[i]], 1);
}

__global__ void scan_kernel() {  // 1 block, 1024 threads
    __shared__ int s[1024];
    const int t = threadIdx.x;
    const int chunk = (NNODES + 1023) / 1024;
    int beg = t * chunk;
    int end = beg + chunk; if (end > NNODES) end = NNODES;
    int sum = 0;
    for (int i = beg; i < end; i++) sum += g_hist[i];
    s[t] = sum;
    __syncthreads();
    for (int d = 1; d < 1024; d <<= 1) {
        int v = (t >= d) ? s[t - d] : 0;
        __syncthreads();
        s[t] += v;
        __syncthreads();
    }
    int run = (t > 0) ? s[t - 1] : 0;
    for (int i = beg; i < end; i++) { g_off[i] = run; run += g_hist[i]; }
    if (t == 0) g_off[NNODES] = NEDGES;
}

__global__ void scatter_kernel(const int* __restrict__ src, const int* __restrict__ dst) {
    int i = blockIdx.x * blockDim.x + threadIdx.x;
    if (i >= NEDGES) return;
    int d = dst[i];
    int p = g_off[d] + atomicAdd(&g_cur[d], 1);
    g_ssrc[p] = src[i];
}

// ---------------- weight preprocessing ---------------------------------------
// g_WpreH[((l*2+h)*128 + n)*128 + k] = fp16( w_pre_l[(h*128+k)*128 + n] )
// plus tf32-round w_out into g_WoR.
#define PREP_W  (2 * 2 * FDIM * FDIM)           // 65536
#define PREP_O  (FDIM * CLS)                    // 5120
__global__ void prep_weights(const float* __restrict__ w1,
                             const float* __restrict__ w2,
                             const float* __restrict__ wo) {
    int i = blockIdx.x * blockDim.x + threadIdx.x;
    if (i < PREP_W) {
        int k = i & 127;
        int n = (i >> 7) & 127;
        int h = (i >> 14) & 1;
        int l = i >> 15;
        const float* w = l ? w2 : w1;
        g_WpreH[i] = __float2half_rn(__ldg(&w[(h * 128 + k) * 128 + n]));
    } else if (i < PREP_W + PREP_O) {
        int j = i - PREP_W;
        g_WoR[j] = tf32r(wo[j]);
    }
}

// ---------------- aggregation (warp/node, float4 lanes, unroll 4) ------------
__global__ void aggregate_kernel() {
    int node = (blockIdx.x * blockDim.x + threadIdx.x) >> 5;
    if (node >= NNODES) return;
    int lane = threadIdx.x & 31;
    int beg = g_off[node], end = g_off[node + 1];
    const float4* Bv = (const float4*)g_B;
    float4 s = make_float4(0.f, 0.f, 0.f, 0.f);
    float4 m = make_float4(-3.4e38f, -3.4e38f, -3.4e38f, -3.4e38f);
    int e = beg;
    for (; e + 3 < end; e += 4) {
        int sv0 = __ldg(&g_ssrc[e]);
        int sv1 = __ldg(&g_ssrc[e + 1]);
        int sv2 = __ldg(&g_ssrc[e + 2]);
        int sv3 = __ldg(&g_ssrc[e + 3]);
        float4 v0 = __ldg(&Bv[(size_t)sv0 * 32 + lane]);
        float4 v1 = __ldg(&Bv[(size_t)sv1 * 32 + lane]);
        float4 v2 = __ldg(&Bv[(size_t)sv2 * 32 + lane]);
        float4 v3 = __ldg(&Bv[(size_t)sv3 * 32 + lane]);
        s.x += (v0.x + v1.x) + (v2.x + v3.x);
        s.y += (v0.y + v1.y) + (v2.y + v3.y);
        s.z += (v0.z + v1.z) + (v2.z + v3.z);
        s.w += (v0.w + v1.w) + (v2.w + v3.w);
        m.x = fmaxf(m.x, fmaxf(fmaxf(v0.x, v1.x), fmaxf(v2.x, v3.x)));
        m.y = fmaxf(m.y, fmaxf(fmaxf(v0.y, v1.y), fmaxf(v2.y, v3.y)));
        m.z = fmaxf(m.z, fmaxf(fmaxf(v0.z, v1.z), fmaxf(v2.z, v3.z)));
        m.w = fmaxf(m.w, fmaxf(fmaxf(v0.w, v1.w), fmaxf(v2.w, v3.w)));
    }
    for (; e < end; e++) {
        int sv = __ldg(&g_ssrc[e]);
        float4 v = __ldg(&Bv[(size_t)sv * 32 + lane]);
        s.x += v.x; s.y += v.y; s.z += v.z; s.w += v.w;
        m.x = fmaxf(m.x, v.x); m.y = fmaxf(m.y, v.y);
        m.z = fmaxf(m.z, v.z); m.w = fmaxf(m.w, v.w);
    }
    size_t o = (size_t)node * 32 + lane;
    float c = (float)(end - beg);
    float ic = 1.f / fmaxf(c, 1.f);
    if (lane == 0) g_IC[node] = ic;
    float4 a = ((const float4*)g_A)[o];
    float4 t;
    t.x = fmaf(c, a.x, s.x); t.y = fmaf(c, a.y, s.y);
    t.z = fmaf(c, a.z, s.z); t.w = fmaf(c, a.w, s.w);
    ((float4*)g_S)[o] = t;
    bool nz = (c > 0.f);
    float4 mx;
    mx.x = nz ? (a.x + m.x) : 0.f; mx.y = nz ? (a.y + m.y) : 0.f;
    mx.z = nz ? (a.z + m.z) : 0.f; mx.w = nz ? (a.w + m.w) : 0.f;
    ((float4*)g_M)[o] = mx;
}

// ---------------- fused post@lin weight: tiled, transposed fp16 output -------
// W'[r][c] = sum_k wpost[r][k]*wlin[k][c]  (r<512);  bias'[c] = b_post@wlin + blin.
// Stored transposed: wfT[c*512 + r] (fp16). Blocks 0..63: 8 rows each; block 64: bias.
__global__ void fuse_kernel(const float* __restrict__ wpost, const float* __restrict__ bpost,
                            const float* __restrict__ wlin,  const float* __restrict__ blin,
                            __half* __restrict__ wfT, float* __restrict__ wfb) {
    __shared__ float srow[8][FDIM];
    const int b = blockIdx.x, c = threadIdx.x;   // 128 threads
    if (b < 64) {
        #pragma unroll
        for (int j = 0; j < 8; j++)
            srow[j][c] = wpost[(size_t)(8 * b + j) * FDIM + c];
        __syncthreads();
        float acc[8] = {};
        #pragma unroll 4
        for (int k = 0; k < FDIM; k++) {
            float wl = wlin[k * FDIM + c];
            #pragma unroll
            for (int j = 0; j < 8; j++) acc[j] = fmaf(srow[j][k], wl, acc[j]);
        }
        #pragma unroll
        for (int j = 0; j < 8; j++)
            wfT[(size_t)c * 512 + 8 * b + j] = __float2half_rn(acc[j]);
    } else {
        srow[0][c] = bpost[c];
        __syncthreads();
        float acc = blin[c];
        #pragma unroll 4
        for (int k = 0; k < FDIM; k++) acc = fmaf(srow[0][k], wlin[k * FDIM + c], acc);
        wfb[c] = acc;
    }
}

// ---------------- fp16 tensor-core GEMM --------------------------------------
// Block 128(M) x 128(N), K-slab 32 (2 x m16n8k16 steps), 2-stage cp.async.
// 8 warps 4(M)x2(N); warp tile 32x64. A: fp32 smem, cvt to fp16 at frag load
// (pairs via float2 -> half2, same 10-bit rounding as tf32). B: fp16 smem,
// loaded from TRANSPOSED fp16 weights [n][k] -> frag k-pairs are single LDS.32,
// conflict-free. SCALE path applies per-row ic (mean segment) before cvt.
#define AST  36              // A smem row stride (fp32)
#define BSTH 72              // B smem row stride (fp16): 64 + 8 pad (144B = 9*16)
#define STGF (128 * AST + 128 * BSTH / 2)   // floats per stage = 9216
#define GSMEM_BYTES (2 * STGF * 4)          // 73728

struct GemmSrcs { const float* s[4]; };

template<bool SCALE>
__device__ __forceinline__ void mma_block_h(const float* __restrict__ As,
                                            const __half* __restrict__ Bs,
                                            float (*acc)[8][4],
                                            int wm, int wn, int fr, int fc,
                                            const float* fs) {
    #pragma unroll
    for (int ks = 0; ks < 32; ks += 16) {
        unsigned a[2][4];
        #pragma unroll
        for (int mt = 0; mt < 2; mt++) {
            int r0 = wm + mt * 16 + fr;
            float2 p0 = *(const float2*)&As[(r0)     * AST + ks + 2 * fc];
            float2 p1 = *(const float2*)&As[(r0 + 8) * AST + ks + 2 * fc];
            float2 p2 = *(const float2*)&As[(r0)     * AST + ks + 2 * fc + 8];
            float2 p3 = *(const float2*)&As[(r0 + 8) * AST + ks + 2 * fc + 8];
            if (SCALE) {
                float f0 = fs[mt * 2], f1 = fs[mt * 2 + 1];
                p0.x *= f0; p0.y *= f0; p2.x *= f0; p2.y *= f0;
                p1.x *= f1; p1.y *= f1; p3.x *= f1; p3.y *= f1;
            }
            a[mt][0] = pack_h2(p0.x, p0.y);
            a[mt][1] = pack_h2(p1.x, p1.y);
            a[mt][2] = pack_h2(p2.x, p2.y);
            a[mt][3] = pack_h2(p3.x, p3.y);
        }
        #pragma unroll
        for (int nt = 0; nt < 8; nt++) {
            int n = wn + nt * 8 + fr;
            unsigned b0 = *(const unsigned*)&Bs[n * BSTH + ks + 2 * fc];
            unsigned b1 = *(const unsigned*)&Bs[n * BSTH + ks + 2 * fc + 8];
            mma_f16(acc[0][nt], a[0], b0, b1);
            mma_f16(acc[1][nt], a[1], b0, b1);
        }
    }
}

__global__ __launch_bounds__(256, 2)
void mma_gemm(GemmSrcs srcs, const __half* __restrict__ W,
              const float* __restrict__ bias0,
              float* outA, float* outB,
              const float* __restrict__ icvec, int meanSeg,
              int M, int nIter, int relu, int ldB) {
    extern __shared__ float smem[];
    const int tid = threadIdx.x;
    const int bm = blockIdx.y * 128;

    const __half* Wb = W;
    float* out = outA;
    const float* bias = bias0;
    if (gridDim.x == 2 && blockIdx.x == 1) {
        Wb = W + 128 * 128;        // second weight half (transposed block)
        out = outB;
        bias = nullptr;
    }

    const int lane = tid & 31, wid = tid >> 5;
    const int wm = (wid >> 1) * 32, wn = (wid & 1) * 64;
    const int fr = lane >> 2, fc = lane & 3;

    float fs[4] = {1.f, 1.f, 1.f, 1.f};
    if (icvec) {
        int r = bm + wm + fr;
        fs[0] = icvec[r];      fs[1] = icvec[r + 8];
        fs[2] = icvec[r + 16]; fs[3] = icvec[r + 24];
    }

    float acc[2][8][4];
    #pragma unroll
    for (int mt = 0; mt < 2; mt++)
        #pragma unroll
        for (int nt = 0; nt < 8; nt++)
            #pragma unroll
            for (int j = 0; j < 4; j++) acc[mt][nt][j] = 0.f;

    auto loadStage = [&](int it, int stage) {
        int k0 = it * 32;
        const float* sp = srcs.s[(k0 >> 7) & 3];
        int kloc = k0 & 127;
        float* As = smem + stage * STGF;
        __half* Bs = (__half*)(As + 128 * AST);
        // A: 128 rows x 32 fp32 = 8 chunks/row -> 4 iters
        #pragma unroll
        for (int i = 0; i < 4; i++) {
            int id = tid + 256 * i;
            int arow = id >> 3, c4 = id & 7;
            bool p = (bm + arow) < M;
            cpasync16(As + arow * AST + c4 * 4,
                      sp + (size_t)(bm + arow) * 128 + kloc + c4 * 4, p);
        }
        // B: 128 n-rows x 32 fp16 = 4 chunks/row -> 2 iters
        #pragma unroll
        for (int i = 0; i < 2; i++) {
            int id = tid + 256 * i;
            int n = id >> 2, c4 = id & 3;
            cpasync16(Bs + n * BSTH + c4 * 8,
                      Wb + (size_t)n * ldB + k0 + c4 * 8, true);
        }
        asm volatile("cp.async.commit_group;" ::: "memory");
    };

    loadStage(0, 0);
    for (int it = 0; it < nIter; ++it) {
        int cur = it & 1;
        if (it + 1 < nIter) {
            loadStage(it + 1, cur ^ 1);
            asm volatile("cp.async.wait_group 1;" ::: "memory");
        } else {
            asm volatile("cp.async.wait_group 0;" ::: "memory");
        }
        __syncthreads();

        const float* As = smem + cur * STGF;
        const __half* Bs = (const __half*)(As + 128 * AST);
        bool ms = (((it * 32) >> 7) == meanSeg);
        if (ms) mma_block_h<true >(As, Bs, acc, wm, wn, fr, fc, fs);
        else    mma_block_h<false>(As, Bs, acc, wm, wn, fr, fc, fs);
        __syncthreads();
    }

    #pragma unroll
    for (int mt = 0; mt < 2; mt++) {
        #pragma unroll
        for (int nt = 0; nt < 8; nt++) {
            int r0 = bm + wm + mt * 16 + fr;
            int cc = wn + nt * 8 + 2 * fc;
            float b0 = 0.f, b1 = 0.f;
            if (bias) { b0 = bias[cc]; b1 = bias[cc + 1]; }
            float v0 = acc[mt][nt][0] + b0, v1 = acc[mt][nt][1] + b1;
            float v2 = acc[mt][nt][2] + b0, v3 = acc[mt][nt][3] + b1;
            if (relu) {
                v0 = fmaxf(v0, 0.f); v1 = fmaxf(v1, 0.f);
                v2 = fmaxf(v2, 0.f); v3 = fmaxf(v3, 0.f);
            }
            if (r0 < M) {
                float2 o = make_float2(v0, v1);
                *(float2*)(out + (size_t)r0 * 128 + cc) = o;
            }
            if (r0 + 8 < M) {
                float2 o = make_float2(v2, v3);
                *(float2*)(out + (size_t)(r0 + 8) * 128 + cc) = o;
            }
        }
    }
}

// ---------------- TF32 MMA output projection: out = H2 @ Wo + b -------------
#define OAST 132
#define OBST 44
#define OSMEM_F (128 * OAST + 128 * OBST)
#define OSMEM_BYTES (OSMEM_F * 4)

__global__ __launch_bounds__(256, 2)
void out_gemm(const float* __restrict__ H2, const float* __restrict__ Wo,
              const float* __restrict__ bias, float* __restrict__ out, int M) {
    extern __shared__ float smem[];
    float* As = smem;
    float* Bs = smem + 128 * OAST;
    const int tid = threadIdx.x;
    const int bm = blockIdx.x * 128;
    const int lane = tid & 31, wid = tid >> 5;
    const int fr = lane >> 2, fc = lane & 3;

    #pragma unroll
    for (int i = 0; i < 16; i++) {
        int id = tid + 256 * i;
        int arow = id >> 5, c4 = id & 31;
        bool p = (bm + arow) < M;
        cpasync16(As + arow * OAST + c4 * 4,
                  H2 + (size_t)(bm + arow) * 128 + c4 * 4, p);
    }
    #pragma unroll
    for (int i = 0; i < 5; i++) {
        int id = tid + 256 * i;
        int wrow = id / 10, c4 = id % 10;
        cpasync16(Bs + wrow * OBST + c4 * 4,
                  Wo + (size_t)wrow * CLS + c4 * 4, true);
    }
    asm volatile("cp.async.commit_group;" ::: "memory");
    asm volatile("cp.async.wait_group 0;" ::: "memory");
    __syncthreads();

    const int m0 = wid * 16;
    float acc[5][4];
    #pragma unroll
    for (int nt = 0; nt < 5; nt++)
        #pragma unroll
        for (int j = 0; j < 4; j++) acc[nt][j] = 0.f;

    #pragma unroll
    for (int kk = 0; kk < 128; kk += 8) {
        unsigned af[4];
        af[0] = tf32u(As[(m0 + fr)     * OAST + kk + fc]);
        af[1] = tf32u(As[(m0 + fr + 8) * OAST + kk + fc]);
        af[2] = tf32u(As[(m0 + fr)     * OAST + kk + fc + 4]);
        af[3] = tf32u(As[(m0 + fr + 8) * OAST + kk + fc + 4]);
        #pragma unroll
        for (int nt = 0; nt < 5; nt++) {
            int n0 = nt * 8;
            unsigned b0 = __float_as_uint(Bs[(kk + fc)     * OBST + n0 + fr]);
            unsigned b1 = __float_as_uint(Bs[(kk + 4 + fc) * OBST + n0 + fr]);
            mma_tf32(acc[nt], af, b0, b1);
        }
    }

    #pragma unroll
    for (int nt = 0; nt < 5; nt++) {
        int r0 = bm + m0 + fr;
        int cc = nt * 8 + 2 * fc;
        float b0 = bias[cc], b1 = bias[cc + 1];
        if (r0 < M) {
            float2 o = make_float2(acc[nt][0] + b0, acc[nt][1] + b1);
            *(float2*)(out + (size_t)r0 * CLS + cc) = o;
        }
        if (r0 + 8 < M) {
            float2 o = make_float2(acc[nt][2] + b0, acc[nt][3] + b1);
            *(float2*)(out + (size_t)(r0 + 8) * CLS + cc) = o;
        }
    }
}

// ---------------- host side -------------------------------------------------
extern "C" void kernel_launch(void* const* d_in, const int* in_sizes, int n_in,
                              void* d_out, int out_size) {
    const float* x      = (const float*)d_in[0];
    const int*   ei     = (const int*)  d_in[1];
    const float* w1_pre = (const float*)d_in[2];
    const float* b1_pre = (const float*)d_in[3];
    const float* w1_post= (const float*)d_in[4];
    const float* b1_post= (const float*)d_in[5];
    const float* w1_lin = (const float*)d_in[6];
    const float* b1_lin = (const float*)d_in[7];
    const float* w2_pre = (const float*)d_in[8];
    const float* b2_pre = (const float*)d_in[9];
    const float* w2_post= (const float*)d_in[10];
    const float* b2_post= (const float*)d_in[11];
    const float* w2_lin = (const float*)d_in[12];
    const float* b2_lin = (const float*)d_in[13];
    const float* w_out  = (const float*)d_in[14];
    const float* b_out  = (const float*)d_in[15];
    float* out = (float*)d_out;

    static int init_done = 0;
    if (!init_done) {
        cudaFuncSetAttribute(mma_gemm, cudaFuncAttributeMaxDynamicSharedMemorySize,
                             GSMEM_BYTES);
        cudaFuncSetAttribute(out_gemm, cudaFuncAttributeMaxDynamicSharedMemorySize,
                             OSMEM_BYTES);
        init_done = 1;
    }

    void *pA, *pB, *pH, *pH2, *pS, *pM, *pIC, *pWpreH, *pWfT1, *pWfT2,
         *pWfb1, *pWfb2, *pWoR, *pHist, *pCur;
    cudaGetSymbolAddress(&pA, g_A);
    cudaGetSymbolAddress(&pB, g_B);
    cudaGetSymbolAddress(&pH, g_H);
    cudaGetSymbolAddress(&pH2, g_H2);
    cudaGetSymbolAddress(&pS, g_S);
    cudaGetSymbolAddress(&pM, g_M);
    cudaGetSymbolAddress(&pIC, g_IC);
    cudaGetSymbolAddress(&pWpreH, g_WpreH);
    cudaGetSymbolAddress(&pWfT1, g_WfT1);
    cudaGetSymbolAddress(&pWfT2, g_WfT2);
    cudaGetSymbolAddress(&pWfb1, g_Wfb1);
    cudaGetSymbolAddress(&pWfb2, g_Wfb2);
    cudaGetSymbolAddress(&pWoR, g_WoR);
    cudaGetSymbolAddress(&pHist, g_hist);
    cudaGetSymbolAddress(&pCur, g_cur);

    const int* srcp = ei;           // edge_index[0]
    const int* dstp = ei + NEDGES;  // edge_index[1]

    // ---- graph preprocessing (single stream, R4 ordering) -------------------
    cudaMemsetAsync(pHist, 0, NNODES * sizeof(int));
    cudaMemsetAsync(pCur,  0, NNODES * sizeof(int));
    hist_kernel<<<(NEDGES + 255) / 256, 256>>>(dstp);
    scan_kernel<<<1, 1024>>>();
    scatter_kernel<<<(NEDGES + 255) / 256, 256>>>(srcp, dstp);

    // ---- weight preprocessing ----------------------------------------------
    prep_weights<<<(PREP_W + PREP_O + 255) / 256, 256>>>(w1_pre, w2_pre, w_out);
    fuse_kernel<<<65, 128>>>(w1_post, b1_post, w1_lin, b1_lin,
                             (__half*)pWfT1, (float*)pWfb1);
    fuse_kernel<<<65, 128>>>(w2_post, b2_post, w2_lin, b2_lin,
                             (__half*)pWfT2, (float*)pWfb2);

    const int MB = (NNODES + 127) / 128;

    // ---- layer 1 -----------------------------------------------------------
    GemmSrcs pre1; pre1.s[0] = x; pre1.s[1] = x; pre1.s[2] = x; pre1.s[3] = x;
    mma_gemm<<<dim3(2, MB), 256, GSMEM_BYTES>>>(
        pre1, (const __half*)pWpreH, b1_pre, (float*)pA, (float*)pB,
        nullptr, -1, NNODES, 128 / 32, 0, 128);
    aggregate_kernel<<<(NNODES + 7) / 8, 256>>>();

    GemmSrcs cat1; cat1.s[0] = x; cat1.s[1] = (const float*)pS;
    cat1.s[2] = (const float*)pM; cat1.s[3] = (const float*)pS;
    mma_gemm<<<dim3(1, MB), 256, GSMEM_BYTES>>>(
        cat1, (const __half*)pWfT1, (const float*)pWfb1,
        (float*)pH, (float*)pH, (const float*)pIC, 1, NNODES, 512 / 32, 1, 512);

    // ---- layer 2 -----------------------------------------------------------
    GemmSrcs pre2; pre2.s[0] = (const float*)pH; pre2.s[1] = pre2.s[0];
    pre2.s[2] = pre2.s[0]; pre2.s[3] = pre2.s[0];
    mma_gemm<<<dim3(2, MB), 256, GSMEM_BYTES>>>(
        pre2, (const __half*)pWpreH + 2 * 128 * 128, b2_pre, (float*)pA, (float*)pB,
        nullptr, -1, NNODES, 128 / 32, 0, 128);
    aggregate_kernel<<<(NNODES + 7) / 8, 256>>>();

    GemmSrcs cat2; cat2.s[0] = (const float*)pH; cat2.s[1] = (const float*)pS;
    cat2.s[2] = (const float*)pM; cat2.s[3] = (const float*)pS;
    mma_gemm<<<dim3(1, MB), 256, GSMEM_BYTES>>>(
        cat2, (const __half*)pWfT2, (const float*)pWfb2,
        (float*)pH2, (float*)pH2, (const float*)pIC, 1, NNODES, 512 / 32, 1, 512);

    // ---- output projection (TF32 MMA) --------------------------------------
    out_gemm<<<(NNODES + 127) / 128, 256, OSMEM_BYTES>>>(
        (const float*)pH2, (const float*)pWoR, b_out, out, NNODES);
}